// round 2
// baseline (speedup 1.0000x reference)
#include <cuda_runtime.h>

#define D_MODEL 1024
#define N_HEADS 16
#define DK      64
#define B_SIZE  2
#define S_LEN   2048
#define M_ROWS  (B_SIZE * S_LEN)   // 4096

// ---------------- scratch (static device globals; no allocation) ----------------
__device__ float g_Qh[B_SIZE * N_HEADS * S_LEN * DK];   // [B,H,S,DK]
__device__ float g_Kh[B_SIZE * N_HEADS * S_LEN * DK];   // [B,H,S,DK] (holds Kh + k_pe)
__device__ float g_Vh[B_SIZE * N_HEADS * S_LEN * DK];   // [B,H,S,DK]
__device__ float g_attn[M_ROWS * D_MODEL];              // [B,S,D] attention output

// =====================================================================
// Projection GEMM: out = X @ W + bias, written head-split.
// Tile 64x64, BK=16, 256 threads, 4x4 micro-tile.
// z=0: Q (mode headsplit), z=1: K (headsplit + k_pe), z=2: V (headsplit)
// =====================================================================
__global__ __launch_bounds__(256) void proj_kernel(
    const float* __restrict__ q, const float* __restrict__ k, const float* __restrict__ v,
    const float* __restrict__ Wq, const float* __restrict__ Wk, const float* __restrict__ Wv,
    const float* __restrict__ bq, const float* __restrict__ bk, const float* __restrict__ bv,
    const float* __restrict__ kpe)
{
    __shared__ float As[16 * 68];   // As[k][m] transposed
    __shared__ float Bs[16 * 68];   // Bs[k][n]

    const int z = blockIdx.z;
    const float* X; const float* W; const float* bias; float* out;
    if (z == 0)      { X = q; W = Wq; bias = bq; out = g_Qh; }
    else if (z == 1) { X = k; W = Wk; bias = bk; out = g_Kh; }
    else             { X = v; W = Wv; bias = bv; out = g_Vh; }

    const int tid = threadIdx.x;
    const int tx = tid & 15, ty = tid >> 4;
    const int n0 = blockIdx.x * 64;
    const int m0 = blockIdx.y * 64;

    const int lrow = tid >> 2, lkq = tid & 3;    // X loader: 64 rows x 4 float4
    const int lk   = tid >> 4, lnq = tid & 15;   // W loader: 16 k x 16 float4

    float acc[4][4];
#pragma unroll
    for (int i = 0; i < 4; i++)
#pragma unroll
        for (int j = 0; j < 4; j++) acc[i][j] = 0.f;

    for (int k0 = 0; k0 < D_MODEL; k0 += 16) {
        __syncthreads();
        // load X tile transposed
        float4 xa = *(const float4*)&X[(size_t)(m0 + lrow) * D_MODEL + k0 + 4 * lkq];
        As[(4 * lkq + 0) * 68 + lrow] = xa.x;
        As[(4 * lkq + 1) * 68 + lrow] = xa.y;
        As[(4 * lkq + 2) * 68 + lrow] = xa.z;
        As[(4 * lkq + 3) * 68 + lrow] = xa.w;
        // load W tile
        *(float4*)&Bs[lk * 68 + 4 * lnq] =
            *(const float4*)&W[(size_t)(k0 + lk) * D_MODEL + n0 + 4 * lnq];
        __syncthreads();

#pragma unroll
        for (int kk = 0; kk < 16; kk++) {
            float4 a = *(float4*)&As[kk * 68 + 4 * ty];
            float4 b = *(float4*)&Bs[kk * 68 + 4 * tx];
            float av[4] = {a.x, a.y, a.z, a.w};
            float bv4[4] = {b.x, b.y, b.z, b.w};
#pragma unroll
            for (int i = 0; i < 4; i++)
#pragma unroll
                for (int j = 0; j < 4; j++) acc[i][j] += av[i] * bv4[j];
        }
    }

    // epilogue: head-split write
    float4 bia = *(const float4*)&bias[n0 + 4 * tx];
    const int h = n0 >> 6;           // whole block is one head (BN==DK==64)
    const int dbase = 4 * tx;
#pragma unroll
    for (int qi = 0; qi < 4; qi++) {
        int m = m0 + 4 * ty + qi;
        int b = m >> 11;             // /2048
        int s = m & 2047;
        float4 r;
        r.x = acc[qi][0] + bia.x;
        r.y = acc[qi][1] + bia.y;
        r.z = acc[qi][2] + bia.z;
        r.w = acc[qi][3] + bia.w;
        if (z == 1) {
            // Keff = Kh + k_pe[h, d, s]; k_pe shape [H, DK, S]
            r.x += kpe[(size_t)(h * DK + dbase + 0) * S_LEN + s];
            r.y += kpe[(size_t)(h * DK + dbase + 1) * S_LEN + s];
            r.z += kpe[(size_t)(h * DK + dbase + 2) * S_LEN + s];
            r.w += kpe[(size_t)(h * DK + dbase + 3) * S_LEN + s];
        }
        *(float4*)&out[(((size_t)b * N_HEADS + h) * S_LEN + s) * DK + dbase] = r;
    }
}

// =====================================================================
// Output projection GEMM: d_out = g_attn @ Wo + bo (plain layout)
// =====================================================================
__global__ __launch_bounds__(256) void outproj_kernel(
    const float* __restrict__ Wo, const float* __restrict__ bo, float* __restrict__ out)
{
    __shared__ float As[16 * 68];
    __shared__ float Bs[16 * 68];

    const int tid = threadIdx.x;
    const int tx = tid & 15, ty = tid >> 4;
    const int n0 = blockIdx.x * 64;
    const int m0 = blockIdx.y * 64;
    const int lrow = tid >> 2, lkq = tid & 3;
    const int lk   = tid >> 4, lnq = tid & 15;

    float acc[4][4];
#pragma unroll
    for (int i = 0; i < 4; i++)
#pragma unroll
        for (int j = 0; j < 4; j++) acc[i][j] = 0.f;

    for (int k0 = 0; k0 < D_MODEL; k0 += 16) {
        __syncthreads();
        float4 xa = *(const float4*)&g_attn[(size_t)(m0 + lrow) * D_MODEL + k0 + 4 * lkq];
        As[(4 * lkq + 0) * 68 + lrow] = xa.x;
        As[(4 * lkq + 1) * 68 + lrow] = xa.y;
        As[(4 * lkq + 2) * 68 + lrow] = xa.z;
        As[(4 * lkq + 3) * 68 + lrow] = xa.w;
        *(float4*)&Bs[lk * 68 + 4 * lnq] =
            *(const float4*)&Wo[(size_t)(k0 + lk) * D_MODEL + n0 + 4 * lnq];
        __syncthreads();

#pragma unroll
        for (int kk = 0; kk < 16; kk++) {
            float4 a = *(float4*)&As[kk * 68 + 4 * ty];
            float4 b = *(float4*)&Bs[kk * 68 + 4 * tx];
            float av[4] = {a.x, a.y, a.z, a.w};
            float bv4[4] = {b.x, b.y, b.z, b.w};
#pragma unroll
            for (int i = 0; i < 4; i++)
#pragma unroll
                for (int j = 0; j < 4; j++) acc[i][j] += av[i] * bv4[j];
        }
    }

    float4 bia = *(const float4*)&bo[n0 + 4 * tx];
#pragma unroll
    for (int qi = 0; qi < 4; qi++) {
        int m = m0 + 4 * ty + qi;
        float4 r;
        r.x = acc[qi][0] + bia.x;
        r.y = acc[qi][1] + bia.y;
        r.z = acc[qi][2] + bia.z;
        r.w = acc[qi][3] + bia.w;
        *(float4*)&out[(size_t)m * D_MODEL + n0 + 4 * tx] = r;
    }
}

// =====================================================================
// Flash attention, fp32. Block = 64 queries x one (b,h). 256 threads.
// Smem (dynamic, ~53KB): Qt[d][q], KVt (Kt[d][t] then Vs[t][d]), Pt[t][q], m/l/corr
// =====================================================================
#define PAD 68
#define ATTN_SMEM_BYTES ((3 * 64 * PAD + 3 * 64) * 4)

__global__ __launch_bounds__(256) void attn_kernel()
{
    extern __shared__ float sm[];
    float* Qt  = sm;                 // [64][PAD]  Qt[d][q], pre-scaled by 1/8
    float* KVt = sm + 64 * PAD;      // [64][PAD]  Kt[d][t] then Vs[t][d]
    float* Pt  = sm + 2 * 64 * PAD;  // [64][PAD]  Pt[t][q]
    float* mrow = sm + 3 * 64 * PAD; // [64]
    float* lrow = mrow + 64;         // [64]
    float* crow = lrow + 64;         // [64]

    const int tid = threadIdx.x;
    const int tx = tid & 15, ty = tid >> 4;
    const int q0 = blockIdx.x * 64;
    const int h = blockIdx.y;
    const int b = blockIdx.z;

    const float* Qbase = g_Qh + (((size_t)b * N_HEADS + h) * S_LEN + q0) * DK;
    const float* Kbase = g_Kh + (((size_t)b * N_HEADS + h) * S_LEN) * DK;
    const float* Vbase = g_Vh + (((size_t)b * N_HEADS + h) * S_LEN) * DK;

    // load Q tile transposed, scaled by 1/sqrt(dk)=0.125
#pragma unroll
    for (int i = 0; i < 16; i++) {
        int idx = tid + i * 256;
        int s = idx >> 6, d = idx & 63;
        Qt[d * PAD + s] = Qbase[s * DK + d] * 0.125f;
    }
    if (tid < 64) { mrow[tid] = -1e30f; lrow[tid] = 0.f; }

    float acc[4][4];
#pragma unroll
    for (int i = 0; i < 4; i++)
#pragma unroll
        for (int j = 0; j < 4; j++) acc[i][j] = 0.f;

    __syncthreads();

    for (int t0 = 0; t0 < S_LEN; t0 += 64) {
        // 1) K tile transposed into KVt
#pragma unroll
        for (int i = 0; i < 16; i++) {
            int idx = tid + i * 256;
            int t = idx >> 6, d = idx & 63;
            KVt[d * PAD + t] = Kbase[(size_t)(t0 + t) * DK + d];
        }
        __syncthreads();

        // 2) scores S = Q*K^T (4x4 micro-tile, contract d)
        float sc[4][4];
#pragma unroll
        for (int i = 0; i < 4; i++)
#pragma unroll
            for (int j = 0; j < 4; j++) sc[i][j] = 0.f;
#pragma unroll
        for (int d = 0; d < 64; d++) {
            float4 a = *(float4*)&Qt[d * PAD + 4 * ty];
            float4 bb = *(float4*)&KVt[d * PAD + 4 * tx];
            float av[4] = {a.x, a.y, a.z, a.w};
            float bv4[4] = {bb.x, bb.y, bb.z, bb.w};
#pragma unroll
            for (int i = 0; i < 4; i++)
#pragma unroll
                for (int j = 0; j < 4; j++) sc[i][j] += av[i] * bv4[j];
        }
        // write raw scores Pt[t][q]
#pragma unroll
        for (int tj = 0; tj < 4; tj++)
#pragma unroll
            for (int qi = 0; qi < 4; qi++)
                Pt[(4 * tx + tj) * PAD + 4 * ty + qi] = sc[qi][tj];
        __syncthreads();

        // 3) online softmax (q-owner: 4 threads per query) + V load
        {
            const int qq = tid >> 2, l4 = tid & 3;
            float mloc = -1e30f;
#pragma unroll
            for (int i = 0; i < 16; i++) {
                float sv = Pt[(l4 * 16 + i) * PAD + qq];
                mloc = fmaxf(mloc, sv);
            }
            mloc = fmaxf(mloc, __shfl_xor_sync(0xffffffffu, mloc, 1));
            mloc = fmaxf(mloc, __shfl_xor_sync(0xffffffffu, mloc, 2));
            float mold = mrow[qq];
            float mnew = fmaxf(mold, mloc);
            float corr = __expf(mold - mnew);
            float lsum = 0.f;
#pragma unroll
            for (int i = 0; i < 16; i++) {
                float sv = Pt[(l4 * 16 + i) * PAD + qq];
                float p = __expf(sv - mnew);
                Pt[(l4 * 16 + i) * PAD + qq] = p;
                lsum += p;
            }
            lsum += __shfl_xor_sync(0xffffffffu, lsum, 1);
            lsum += __shfl_xor_sync(0xffffffffu, lsum, 2);
            if (l4 == 0) {
                lrow[qq] = lrow[qq] * corr + lsum;
                mrow[qq] = mnew;
                crow[qq] = corr;
            }
            // V tile (natural layout) into KVt
#pragma unroll
            for (int i = 0; i < 16; i++) {
                int idx = tid + i * 256;
                int t = idx >> 6, d = idx & 63;
                KVt[t * PAD + d] = Vbase[(size_t)(t0 + t) * DK + d];
            }
        }
        __syncthreads();

        // 4) rescale accumulators, accumulate P @ V (4x4 micro-tile, contract t)
        float cf[4];
#pragma unroll
        for (int qi = 0; qi < 4; qi++) cf[qi] = crow[4 * ty + qi];
#pragma unroll
        for (int qi = 0; qi < 4; qi++)
#pragma unroll
            for (int j = 0; j < 4; j++) acc[qi][j] *= cf[qi];
#pragma unroll
        for (int t = 0; t < 64; t++) {
            float4 p = *(float4*)&Pt[t * PAD + 4 * ty];
            float4 vv = *(float4*)&KVt[t * PAD + 4 * tx];
            float pv[4] = {p.x, p.y, p.z, p.w};
            float vv4[4] = {vv.x, vv.y, vv.z, vv.w};
#pragma unroll
            for (int qi = 0; qi < 4; qi++)
#pragma unroll
                for (int j = 0; j < 4; j++) acc[qi][j] += pv[qi] * vv4[j];
        }
        __syncthreads();
    }

    // epilogue: normalize and write to g_attn [B,S,D] with column block h*64
#pragma unroll
    for (int qi = 0; qi < 4; qi++) {
        int s = q0 + 4 * ty + qi;
        float inv = 1.f / lrow[4 * ty + qi];
        float4 r;
        r.x = acc[qi][0] * inv;
        r.y = acc[qi][1] * inv;
        r.z = acc[qi][2] * inv;
        r.w = acc[qi][3] * inv;
        *(float4*)&g_attn[((size_t)b * S_LEN + s) * D_MODEL + h * DK + 4 * tx] = r;
    }
}

// =====================================================================
extern "C" void kernel_launch(void* const* d_in, const int* in_sizes, int n_in,
                              void* d_out, int out_size)
{
    const float* q   = (const float*)d_in[0];
    const float* k   = (const float*)d_in[1];
    const float* v   = (const float*)d_in[2];
    const float* kpe = (const float*)d_in[3];
    const float* Wq  = (const float*)d_in[4];
    const float* bq  = (const float*)d_in[5];
    const float* Wk  = (const float*)d_in[6];
    const float* bk  = (const float*)d_in[7];
    const float* Wv  = (const float*)d_in[8];
    const float* bv  = (const float*)d_in[9];
    const float* Wo  = (const float*)d_in[10];
    const float* bo  = (const float*)d_in[11];
    float* out = (float*)d_out;

    // attention kernel needs >48KB dynamic smem
    cudaFuncSetAttribute(attn_kernel, cudaFuncAttributeMaxDynamicSharedMemorySize,
                         ATTN_SMEM_BYTES);

    dim3 gp(D_MODEL / 64, M_ROWS / 64, 3);
    proj_kernel<<<gp, 256>>>(q, k, v, Wq, Wk, Wv, bq, bk, bv, kpe);

    dim3 ga(S_LEN / 64, N_HEADS, B_SIZE);
    attn_kernel<<<ga, 256, ATTN_SMEM_BYTES>>>();

    dim3 go(D_MODEL / 64, M_ROWS / 64, 1);
    outproj_kernel<<<go, 256>>>(Wo, bo, out);
}

// round 4
// speedup vs baseline: 1.2427x; 1.2427x over previous
#include <cuda_runtime.h>
#include <cuda_bf16.h>
#include <cstdint>

#define D_MODEL 1024
#define N_HEADS 16
#define DK      64
#define B_SIZE  2
#define S_LEN   2048
#define M_ROWS  (B_SIZE * S_LEN)   // 4096

// ---------------- scratch ----------------
__device__ float g_Qh[B_SIZE * N_HEADS * S_LEN * DK];
__device__ float g_Kh[B_SIZE * N_HEADS * S_LEN * DK];
__device__ float g_Vh[B_SIZE * N_HEADS * S_LEN * DK];
__device__ float g_attn[M_ROWS * D_MODEL];

__device__ __nv_bfloat16 g_Ah[3][(size_t)M_ROWS * D_MODEL];
__device__ __nv_bfloat16 g_Al[3][(size_t)M_ROWS * D_MODEL];
__device__ __nv_bfloat16 g_Oh[(size_t)M_ROWS * D_MODEL];
__device__ __nv_bfloat16 g_Ol[(size_t)M_ROWS * D_MODEL];
__device__ __nv_bfloat16 g_Wth[4][(size_t)D_MODEL * D_MODEL]; // W^T hi [n][k]
__device__ __nv_bfloat16 g_Wtl[4][(size_t)D_MODEL * D_MODEL]; // W^T lo [n][k]

// ======================= helpers =======================
__device__ __forceinline__ uint32_t smem_u32(const void* p) {
    uint32_t a;
    asm("{ .reg .u64 t; cvta.to.shared.u64 t, %1; cvt.u32.u64 %0, t; }" : "=r"(a) : "l"(p));
    return a;
}
__device__ __forceinline__ void cp16(uint32_t dst, const void* src) {
    asm volatile("cp.async.cg.shared.global [%0], [%1], 16;" :: "r"(dst), "l"(src));
}
__device__ __forceinline__ void ldsm_x4(uint32_t& r0, uint32_t& r1, uint32_t& r2, uint32_t& r3, uint32_t addr) {
    asm volatile("ldmatrix.sync.aligned.m8n8.x4.shared.b16 {%0,%1,%2,%3}, [%4];"
        : "=r"(r0), "=r"(r1), "=r"(r2), "=r"(r3) : "r"(addr));
}
__device__ __forceinline__ void ldsm_x2(uint32_t& r0, uint32_t& r1, uint32_t addr) {
    asm volatile("ldmatrix.sync.aligned.m8n8.x2.shared.b16 {%0,%1}, [%2];"
        : "=r"(r0), "=r"(r1) : "r"(addr));
}
__device__ __forceinline__ void mma_bf16(float* c, const uint32_t* a, uint32_t b0, uint32_t b1) {
    asm volatile("mma.sync.aligned.m16n8k16.row.col.f32.bf16.bf16.f32 "
        "{%0,%1,%2,%3}, {%4,%5,%6,%7}, {%8,%9}, {%0,%1,%2,%3};"
        : "+f"(c[0]), "+f"(c[1]), "+f"(c[2]), "+f"(c[3])
        : "r"(a[0]), "r"(a[1]), "r"(a[2]), "r"(a[3]), "r"(b0), "r"(b1));
}

// ======================= split prep kernels =======================
__device__ __forceinline__ void split1(float x, __nv_bfloat16& h, __nv_bfloat16& l) {
    h = __float2bfloat16_rn(x);
    l = __float2bfloat16_rn(x - __bfloat162float(h));
}

__global__ __launch_bounds__(256) void split_qkv_kernel(
    const float* __restrict__ q, const float* __restrict__ k, const float* __restrict__ v)
{
    int z = blockIdx.y;
    const float* src = (z == 0) ? q : (z == 1) ? k : v;
    __nv_bfloat16* hi = g_Ah[z];
    __nv_bfloat16* lo = g_Al[z];
    size_t i = ((size_t)blockIdx.x * 256 + threadIdx.x) * 4;
    float4 a = *(const float4*)(src + i);
    __nv_bfloat16 h0,h1,h2,h3,l0,l1,l2,l3;
    split1(a.x,h0,l0); split1(a.y,h1,l1); split1(a.z,h2,l2); split1(a.w,h3,l3);
    *(__nv_bfloat162*)(hi+i)   = __nv_bfloat162(h0,h1);
    *(__nv_bfloat162*)(hi+i+2) = __nv_bfloat162(h2,h3);
    *(__nv_bfloat162*)(lo+i)   = __nv_bfloat162(l0,l1);
    *(__nv_bfloat162*)(lo+i+2) = __nv_bfloat162(l2,l3);
}

__global__ __launch_bounds__(256) void split_o_kernel()
{
    size_t i = ((size_t)blockIdx.x * 256 + threadIdx.x) * 4;
    float4 a = *(const float4*)(g_attn + i);
    __nv_bfloat16 h0,h1,h2,h3,l0,l1,l2,l3;
    split1(a.x,h0,l0); split1(a.y,h1,l1); split1(a.z,h2,l2); split1(a.w,h3,l3);
    *(__nv_bfloat162*)(g_Oh+i)   = __nv_bfloat162(h0,h1);
    *(__nv_bfloat162*)(g_Oh+i+2) = __nv_bfloat162(h2,h3);
    *(__nv_bfloat162*)(g_Ol+i)   = __nv_bfloat162(l0,l1);
    *(__nv_bfloat162*)(g_Ol+i+2) = __nv_bfloat162(l2,l3);
}

__global__ void splitW_kernel(
    const float* __restrict__ Wq, const float* __restrict__ Wk,
    const float* __restrict__ Wv, const float* __restrict__ Wo)
{
    __shared__ float sm[32][33];
    int z = blockIdx.z;
    const float* W = (z == 0) ? Wq : (z == 1) ? Wk : (z == 2) ? Wv : Wo;
    int n0 = blockIdx.x * 32, k0 = blockIdx.y * 32;
    int tx = threadIdx.x, ty = threadIdx.y;
#pragma unroll
    for (int i = 0; i < 4; i++)
        sm[ty + 8 * i][tx] = W[(size_t)(k0 + ty + 8 * i) * D_MODEL + n0 + tx];
    __syncthreads();
#pragma unroll
    for (int i = 0; i < 4; i++) {
        int c = ty + 8 * i;
        float vv = sm[tx][c];
        __nv_bfloat16 h, l;
        split1(vv, h, l);
        size_t o = (size_t)(n0 + c) * D_MODEL + k0 + tx;
        g_Wth[z][o] = h;
        g_Wtl[z][o] = l;
    }
}

// ======================= mma.sync bf16 split GEMM =======================
// C[128x128] = Ah*Wh + Ah*Wl + Al*Wh; K = 3 passes x 1024, BK=32 (96 steps).
// 256 threads = 8 warps, warp grid 2(m) x 4(n), warp tile 64x32.
#define BM 128
#define BN 128
#define BK 32
#define KSTRIDE 40   // bf16 elements per smem row (80B, 16B-aligned, conflict-free)

__global__ __launch_bounds__(256)
void gemm_bf16_kernel(int mode, const float* __restrict__ kpe,
                      const float* __restrict__ bq, const float* __restrict__ bk,
                      const float* __restrict__ bv, const float* __restrict__ bo,
                      float* __restrict__ out_final)
{
    __shared__ __nv_bfloat16 sA[2][BM * KSTRIDE];
    __shared__ __nv_bfloat16 sB[2][BN * KSTRIDE];

    const int z = blockIdx.z;
    const __nv_bfloat16 *Ahp, *Alp, *Whp, *Wlp;
    const float* bias;
    if (mode == 0) {
        Ahp = g_Ah[z]; Alp = g_Al[z]; Whp = g_Wth[z]; Wlp = g_Wtl[z];
        bias = (z == 0) ? bq : (z == 1) ? bk : bv;
    } else {
        Ahp = g_Oh; Alp = g_Ol; Whp = g_Wth[3]; Wlp = g_Wtl[3];
        bias = bo;
    }

    const int m0 = blockIdx.y * BM;
    const int n0 = blockIdx.x * BN;
    const int tid = threadIdx.x;
    const int wid = tid >> 5, lane = tid & 31;
    const int wm = wid & 1, wn = wid >> 1;   // warp tile: rows wm*64, cols wn*32

    const uint32_t sA0 = smem_u32(sA[0]);
    const uint32_t sB0 = smem_u32(sB[0]);

    // loader mapping: row = tid>>1 (0..127), cpair = tid&1 -> two 16B chunks
    const int lrow = tid >> 1, lcp = tid & 1;

    auto load_step = [&](int step, int buf) {
        int p = step >> 5, kc = (step & 31) * BK;
        const __nv_bfloat16* As = (p < 2) ? Ahp : Alp;
        const __nv_bfloat16* Bs = (p == 1) ? Wlp : Whp;
        const __nv_bfloat16* ag = As + (size_t)(m0 + lrow) * D_MODEL + kc + lcp * 16;
        const __nv_bfloat16* bg = Bs + (size_t)(n0 + lrow) * D_MODEL + kc + lcp * 16;
        uint32_t sa = sA0 + buf * (BM * KSTRIDE * 2) + (lrow * KSTRIDE + lcp * 16) * 2;
        uint32_t sb = sB0 + buf * (BN * KSTRIDE * 2) + (lrow * KSTRIDE + lcp * 16) * 2;
        cp16(sa, ag);       cp16(sa + 16, ag + 8);
        cp16(sb, bg);       cp16(sb + 16, bg + 8);
        asm volatile("cp.async.commit_group;" ::: "memory");
    };

    float acc[4][4][4];
#pragma unroll
    for (int i = 0; i < 4; i++)
#pragma unroll
        for (int j = 0; j < 4; j++)
#pragma unroll
            for (int c = 0; c < 4; c++) acc[i][j][c] = 0.f;

    load_step(0, 0);
    load_step(1, 1);

    const int a_row = (lane & 15), a_koff = (lane >> 4) * 8;
    const int b_row = (lane & 7),  b_koff = ((lane >> 3) & 1) * 8;

    for (int step = 0; step < 96; step++) {
        const int buf = step & 1;
        if (step < 95) asm volatile("cp.async.wait_group 1;" ::: "memory");
        else           asm volatile("cp.async.wait_group 0;" ::: "memory");
        __syncthreads();

        const uint32_t abase = sA0 + buf * (BM * KSTRIDE * 2);
        const uint32_t bbase = sB0 + buf * (BN * KSTRIDE * 2);
#pragma unroll
        for (int k16 = 0; k16 < BK; k16 += 16) {
            uint32_t a[4][4];
#pragma unroll
            for (int mi = 0; mi < 4; mi++)
                ldsm_x4(a[mi][0], a[mi][1], a[mi][2], a[mi][3],
                        abase + ((wm * 64 + mi * 16 + a_row) * KSTRIDE + k16 + a_koff) * 2);
#pragma unroll
            for (int ni = 0; ni < 4; ni++) {
                uint32_t b0, b1;
                ldsm_x2(b0, b1,
                        bbase + ((wn * 32 + ni * 8 + b_row) * KSTRIDE + k16 + b_koff) * 2);
#pragma unroll
                for (int mi = 0; mi < 4; mi++)
                    mma_bf16(acc[mi][ni], a[mi], b0, b1);
            }
        }
        __syncthreads();
        if (step + 2 < 96) load_step(step + 2, buf);
    }

    // ---------------- epilogue (register accumulators) ----------------
    const int gid = lane >> 2, tig = lane & 3;
#pragma unroll
    for (int mi = 0; mi < 4; mi++) {
#pragma unroll
        for (int half = 0; half < 2; half++) {
            const int m = m0 + wm * 64 + mi * 16 + gid + half * 8;
            const int bb = m >> 11, s = m & 2047;
#pragma unroll
            for (int ni = 0; ni < 4; ni++) {
                const int n = n0 + wn * 32 + ni * 8 + tig * 2;
                float c0 = acc[mi][ni][half * 2 + 0] + bias[n];
                float c1 = acc[mi][ni][half * 2 + 1] + bias[n + 1];
                if (mode == 0) {
                    const int h = n >> 6, d = n & 63;
                    if (z == 1) {
                        c0 += kpe[((size_t)h * DK + d) * S_LEN + s];
                        c1 += kpe[((size_t)h * DK + d + 1) * S_LEN + s];
                    }
                    float* outp = (z == 0) ? g_Qh : (z == 1) ? g_Kh : g_Vh;
                    *(float2*)&outp[(((size_t)bb * N_HEADS + h) * S_LEN + s) * DK + d] =
                        make_float2(c0, c1);
                } else {
                    *(float2*)&out_final[(size_t)m * D_MODEL + n] = make_float2(c0, c1);
                }
            }
        }
    }
}

// ======================= flash attention (fp32, unchanged) =======================
#define PAD 68
#define ATTN_SMEM_BYTES ((3 * 64 * PAD + 3 * 64) * 4)

__global__ __launch_bounds__(256) void attn_kernel()
{
    extern __shared__ float sm[];
    float* Qt  = sm;
    float* KVt = sm + 64 * PAD;
    float* Pt  = sm + 2 * 64 * PAD;
    float* mrow = sm + 3 * 64 * PAD;
    float* lrow = mrow + 64;
    float* crow = lrow + 64;

    const int tid = threadIdx.x;
    const int tx = tid & 15, ty = tid >> 4;
    const int q0 = blockIdx.x * 64;
    const int h = blockIdx.y;
    const int b = blockIdx.z;

    const float* Qbase = g_Qh + (((size_t)b * N_HEADS + h) * S_LEN + q0) * DK;
    const float* Kbase = g_Kh + (((size_t)b * N_HEADS + h) * S_LEN) * DK;
    const float* Vbase = g_Vh + (((size_t)b * N_HEADS + h) * S_LEN) * DK;

#pragma unroll
    for (int i = 0; i < 16; i++) {
        int idx = tid + i * 256;
        int s = idx >> 6, d = idx & 63;
        Qt[d * PAD + s] = Qbase[s * DK + d] * 0.125f;
    }
    if (tid < 64) { mrow[tid] = -1e30f; lrow[tid] = 0.f; }

    float acc[4][4];
#pragma unroll
    for (int i = 0; i < 4; i++)
#pragma unroll
        for (int j = 0; j < 4; j++) acc[i][j] = 0.f;

    __syncthreads();

    for (int t0 = 0; t0 < S_LEN; t0 += 64) {
#pragma unroll
        for (int i = 0; i < 16; i++) {
            int idx = tid + i * 256;
            int t = idx >> 6, d = idx & 63;
            KVt[d * PAD + t] = Kbase[(size_t)(t0 + t) * DK + d];
        }
        __syncthreads();

        float sc[4][4];
#pragma unroll
        for (int i = 0; i < 4; i++)
#pragma unroll
            for (int j = 0; j < 4; j++) sc[i][j] = 0.f;
#pragma unroll
        for (int d = 0; d < 64; d++) {
            float4 a = *(float4*)&Qt[d * PAD + 4 * ty];
            float4 bb = *(float4*)&KVt[d * PAD + 4 * tx];
            float av[4] = {a.x, a.y, a.z, a.w};
            float bv4[4] = {bb.x, bb.y, bb.z, bb.w};
#pragma unroll
            for (int i = 0; i < 4; i++)
#pragma unroll
                for (int j = 0; j < 4; j++) sc[i][j] += av[i] * bv4[j];
        }
#pragma unroll
        for (int tj = 0; tj < 4; tj++)
#pragma unroll
            for (int qi = 0; qi < 4; qi++)
                Pt[(4 * tx + tj) * PAD + 4 * ty + qi] = sc[qi][tj];
        __syncthreads();

        {
            const int qq = tid >> 2, l4 = tid & 3;
            float mloc = -1e30f;
#pragma unroll
            for (int i = 0; i < 16; i++)
                mloc = fmaxf(mloc, Pt[(l4 * 16 + i) * PAD + qq]);
            mloc = fmaxf(mloc, __shfl_xor_sync(0xffffffffu, mloc, 1));
            mloc = fmaxf(mloc, __shfl_xor_sync(0xffffffffu, mloc, 2));
            float mold = mrow[qq];
            float mnew = fmaxf(mold, mloc);
            float corr = __expf(mold - mnew);
            float lsum = 0.f;
#pragma unroll
            for (int i = 0; i < 16; i++) {
                float p = __expf(Pt[(l4 * 16 + i) * PAD + qq] - mnew);
                Pt[(l4 * 16 + i) * PAD + qq] = p;
                lsum += p;
            }
            lsum += __shfl_xor_sync(0xffffffffu, lsum, 1);
            lsum += __shfl_xor_sync(0xffffffffu, lsum, 2);
            if (l4 == 0) {
                lrow[qq] = lrow[qq] * corr + lsum;
                mrow[qq] = mnew;
                crow[qq] = corr;
            }
#pragma unroll
            for (int i = 0; i < 16; i++) {
                int idx = tid + i * 256;
                int t = idx >> 6, d = idx & 63;
                KVt[t * PAD + d] = Vbase[(size_t)(t0 + t) * DK + d];
            }
        }
        __syncthreads();

        float cf[4];
#pragma unroll
        for (int qi = 0; qi < 4; qi++) cf[qi] = crow[4 * ty + qi];
#pragma unroll
        for (int qi = 0; qi < 4; qi++)
#pragma unroll
            for (int j = 0; j < 4; j++) acc[qi][j] *= cf[qi];
#pragma unroll
        for (int t = 0; t < 64; t++) {
            float4 p = *(float4*)&Pt[t * PAD + 4 * ty];
            float4 vv = *(float4*)&KVt[t * PAD + 4 * tx];
            float pv[4] = {p.x, p.y, p.z, p.w};
            float vv4[4] = {vv.x, vv.y, vv.z, vv.w};
#pragma unroll
            for (int qi = 0; qi < 4; qi++)
#pragma unroll
                for (int j = 0; j < 4; j++) acc[qi][j] += pv[qi] * vv4[j];
        }
        __syncthreads();
    }

#pragma unroll
    for (int qi = 0; qi < 4; qi++) {
        int s = q0 + 4 * ty + qi;
        float inv = 1.f / lrow[4 * ty + qi];
        float4 r;
        r.x = acc[qi][0] * inv;
        r.y = acc[qi][1] * inv;
        r.z = acc[qi][2] * inv;
        r.w = acc[qi][3] * inv;
        *(float4*)&g_attn[((size_t)b * S_LEN + s) * D_MODEL + h * DK + 4 * tx] = r;
    }
}

// =====================================================================
extern "C" void kernel_launch(void* const* d_in, const int* in_sizes, int n_in,
                              void* d_out, int out_size)
{
    const float* q   = (const float*)d_in[0];
    const float* k   = (const float*)d_in[1];
    const float* v   = (const float*)d_in[2];
    const float* kpe = (const float*)d_in[3];
    const float* Wq  = (const float*)d_in[4];
    const float* bq  = (const float*)d_in[5];
    const float* Wk  = (const float*)d_in[6];
    const float* bk  = (const float*)d_in[7];
    const float* Wv  = (const float*)d_in[8];
    const float* bv  = (const float*)d_in[9];
    const float* Wo  = (const float*)d_in[10];
    const float* bo  = (const float*)d_in[11];
    float* out = (float*)d_out;

    cudaFuncSetAttribute(attn_kernel, cudaFuncAttributeMaxDynamicSharedMemorySize,
                         ATTN_SMEM_BYTES);

    // prep: split inputs + weights to bf16 hi/lo
    dim3 gs(M_ROWS * D_MODEL / 1024, 3);
    split_qkv_kernel<<<gs, 256>>>(q, k, v);
    dim3 gw(32, 32, 4);
    splitW_kernel<<<gw, dim3(32, 8)>>>(Wq, Wk, Wv, Wo);

    // Q/K/V projections (tensor cores via mma.sync)
    dim3 gp(D_MODEL / BN, M_ROWS / BM, 3);
    gemm_bf16_kernel<<<gp, 256>>>(0, kpe, bq, bk, bv, bo, out);

    // attention
    dim3 ga(S_LEN / 64, N_HEADS, B_SIZE);
    attn_kernel<<<ga, 256, ATTN_SMEM_BYTES>>>();

    // output projection
    split_o_kernel<<<M_ROWS * D_MODEL / 1024, 256>>>();
    dim3 go(D_MODEL / BN, M_ROWS / BM, 1);
    gemm_bf16_kernel<<<go, 256>>>(1, kpe, bq, bk, bv, bo, out);
}

// round 5
// speedup vs baseline: 1.6298x; 1.3115x over previous
#include <cuda_runtime.h>
#include <cuda_bf16.h>
#include <cstdint>

#define D_MODEL 1024
#define N_HEADS 16
#define DK      64
#define B_SIZE  2
#define S_LEN   2048
#define M_ROWS  (B_SIZE * S_LEN)   // 4096

// ---------------- scratch ----------------
__device__ float g_Vh[B_SIZE * N_HEADS * S_LEN * DK];          // V head-split fp32 (pre-transpose)

__device__ __nv_bfloat16 g_Ah[3][(size_t)M_ROWS * D_MODEL];
__device__ __nv_bfloat16 g_Al[3][(size_t)M_ROWS * D_MODEL];
__device__ __nv_bfloat16 g_Oh[(size_t)M_ROWS * D_MODEL];       // attn out hi
__device__ __nv_bfloat16 g_Ol[(size_t)M_ROWS * D_MODEL];       // attn out lo
__device__ __nv_bfloat16 g_Wth[4][(size_t)D_MODEL * D_MODEL];  // W^T hi [n][k]
__device__ __nv_bfloat16 g_Wtl[4][(size_t)D_MODEL * D_MODEL];  // W^T lo [n][k]

// attention operands (bf16 split)
__device__ __nv_bfloat16 g_Qbh[(size_t)M_ROWS * D_MODEL];      // [B,H,S,DK] hi, scaled 1/8
__device__ __nv_bfloat16 g_Qbl[(size_t)M_ROWS * D_MODEL];
__device__ __nv_bfloat16 g_Kbh[(size_t)M_ROWS * D_MODEL];      // [B,H,S,DK] hi (K + kpe)
__device__ __nv_bfloat16 g_Kbl[(size_t)M_ROWS * D_MODEL];
__device__ __nv_bfloat16 g_Vth[(size_t)M_ROWS * D_MODEL];      // [B,H,DK,S] hi (transposed)
__device__ __nv_bfloat16 g_Vtl[(size_t)M_ROWS * D_MODEL];

// ======================= helpers =======================
__device__ __forceinline__ uint32_t smem_u32(const void* p) {
    uint32_t a;
    asm("{ .reg .u64 t; cvta.to.shared.u64 t, %1; cvt.u32.u64 %0, t; }" : "=r"(a) : "l"(p));
    return a;
}
__device__ __forceinline__ void cp16(uint32_t dst, const void* src) {
    asm volatile("cp.async.cg.shared.global [%0], [%1], 16;" :: "r"(dst), "l"(src));
}
__device__ __forceinline__ void ldsm_x4(uint32_t& r0, uint32_t& r1, uint32_t& r2, uint32_t& r3, uint32_t addr) {
    asm volatile("ldmatrix.sync.aligned.m8n8.x4.shared.b16 {%0,%1,%2,%3}, [%4];"
        : "=r"(r0), "=r"(r1), "=r"(r2), "=r"(r3) : "r"(addr));
}
__device__ __forceinline__ void ldsm_x2(uint32_t& r0, uint32_t& r1, uint32_t addr) {
    asm volatile("ldmatrix.sync.aligned.m8n8.x2.shared.b16 {%0,%1}, [%2];"
        : "=r"(r0), "=r"(r1) : "r"(addr));
}
__device__ __forceinline__ void mma_bf16(float* c, const uint32_t* a, uint32_t b0, uint32_t b1) {
    asm volatile("mma.sync.aligned.m16n8k16.row.col.f32.bf16.bf16.f32 "
        "{%0,%1,%2,%3}, {%4,%5,%6,%7}, {%8,%9}, {%0,%1,%2,%3};"
        : "+f"(c[0]), "+f"(c[1]), "+f"(c[2]), "+f"(c[3])
        : "r"(a[0]), "r"(a[1]), "r"(a[2]), "r"(a[3]), "r"(b0), "r"(b1));
}
__device__ __forceinline__ void split1(float x, __nv_bfloat16& h, __nv_bfloat16& l) {
    h = __float2bfloat16_rn(x);
    l = __float2bfloat16_rn(x - __bfloat162float(h));
}

// ======================= split prep kernels =======================
__global__ __launch_bounds__(256) void split_qkv_kernel(
    const float* __restrict__ q, const float* __restrict__ k, const float* __restrict__ v)
{
    int z = blockIdx.y;
    const float* src = (z == 0) ? q : (z == 1) ? k : v;
    __nv_bfloat16* hi = g_Ah[z];
    __nv_bfloat16* lo = g_Al[z];
    size_t i = ((size_t)blockIdx.x * 256 + threadIdx.x) * 4;
    float4 a = *(const float4*)(src + i);
    __nv_bfloat16 h0,h1,h2,h3,l0,l1,l2,l3;
    split1(a.x,h0,l0); split1(a.y,h1,l1); split1(a.z,h2,l2); split1(a.w,h3,l3);
    *(__nv_bfloat162*)(hi+i)   = __nv_bfloat162(h0,h1);
    *(__nv_bfloat162*)(hi+i+2) = __nv_bfloat162(h2,h3);
    *(__nv_bfloat162*)(lo+i)   = __nv_bfloat162(l0,l1);
    *(__nv_bfloat162*)(lo+i+2) = __nv_bfloat162(l2,l3);
}

__global__ void splitW_kernel(
    const float* __restrict__ Wq, const float* __restrict__ Wk,
    const float* __restrict__ Wv, const float* __restrict__ Wo)
{
    __shared__ float sm[32][33];
    int z = blockIdx.z;
    const float* W = (z == 0) ? Wq : (z == 1) ? Wk : (z == 2) ? Wv : Wo;
    int n0 = blockIdx.x * 32, k0 = blockIdx.y * 32;
    int tx = threadIdx.x, ty = threadIdx.y;
#pragma unroll
    for (int i = 0; i < 4; i++)
        sm[ty + 8 * i][tx] = W[(size_t)(k0 + ty + 8 * i) * D_MODEL + n0 + tx];
    __syncthreads();
#pragma unroll
    for (int i = 0; i < 4; i++) {
        int c = ty + 8 * i;
        float vv = sm[tx][c];
        __nv_bfloat16 h, l;
        split1(vv, h, l);
        size_t o = (size_t)(n0 + c) * D_MODEL + k0 + tx;
        g_Wth[z][o] = h;
        g_Wtl[z][o] = l;
    }
}

// V transpose + split: g_Vh [B,H,S,DK] fp32 -> g_Vth/g_Vtl [B,H,DK,S] bf16
__global__ void vtrans_kernel()
{
    __shared__ float sm[32][33];
    int bh = blockIdx.z;
    int d0 = blockIdx.x * 32, s0 = blockIdx.y * 32;
    int tx = threadIdx.x, ty = threadIdx.y;
#pragma unroll
    for (int i = 0; i < 4; i++)
        sm[ty + 8 * i][tx] = g_Vh[((size_t)bh * S_LEN + s0 + ty + 8 * i) * DK + d0 + tx];
    __syncthreads();
#pragma unroll
    for (int i = 0; i < 4; i++) {
        int dl = ty + 8 * i;
        float vv = sm[tx][dl];
        __nv_bfloat16 h, l;
        split1(vv, h, l);
        size_t o = ((size_t)bh * DK + d0 + dl) * S_LEN + s0 + tx;
        g_Vth[o] = h;
        g_Vtl[o] = l;
    }
}

// ======================= mma.sync bf16 split GEMM =======================
#define BM 128
#define BN 128
#define BK 32
#define KSTRIDE 40

__global__ __launch_bounds__(256)
void gemm_bf16_kernel(int mode, const float* __restrict__ kpe,
                      const float* __restrict__ bq, const float* __restrict__ bk,
                      const float* __restrict__ bv, const float* __restrict__ bo,
                      float* __restrict__ out_final)
{
    __shared__ __nv_bfloat16 sA[2][BM * KSTRIDE];
    __shared__ __nv_bfloat16 sB[2][BN * KSTRIDE];

    const int z = blockIdx.z;
    const __nv_bfloat16 *Ahp, *Alp, *Whp, *Wlp;
    const float* bias;
    if (mode == 0) {
        Ahp = g_Ah[z]; Alp = g_Al[z]; Whp = g_Wth[z]; Wlp = g_Wtl[z];
        bias = (z == 0) ? bq : (z == 1) ? bk : bv;
    } else {
        Ahp = g_Oh; Alp = g_Ol; Whp = g_Wth[3]; Wlp = g_Wtl[3];
        bias = bo;
    }

    const int m0 = blockIdx.y * BM;
    const int n0 = blockIdx.x * BN;
    const int tid = threadIdx.x;
    const int wid = tid >> 5, lane = tid & 31;
    const int wm = wid & 1, wn = wid >> 1;

    const uint32_t sA0 = smem_u32(sA[0]);
    const uint32_t sB0 = smem_u32(sB[0]);
    const int lrow = tid >> 1, lcp = tid & 1;

    auto load_step = [&](int step, int buf) {
        int p = step >> 5, kc = (step & 31) * BK;
        const __nv_bfloat16* As = (p < 2) ? Ahp : Alp;
        const __nv_bfloat16* Bs = (p == 1) ? Wlp : Whp;
        const __nv_bfloat16* ag = As + (size_t)(m0 + lrow) * D_MODEL + kc + lcp * 16;
        const __nv_bfloat16* bg = Bs + (size_t)(n0 + lrow) * D_MODEL + kc + lcp * 16;
        uint32_t sa = sA0 + buf * (BM * KSTRIDE * 2) + (lrow * KSTRIDE + lcp * 16) * 2;
        uint32_t sb = sB0 + buf * (BN * KSTRIDE * 2) + (lrow * KSTRIDE + lcp * 16) * 2;
        cp16(sa, ag);       cp16(sa + 16, ag + 8);
        cp16(sb, bg);       cp16(sb + 16, bg + 8);
        asm volatile("cp.async.commit_group;" ::: "memory");
    };

    float acc[4][4][4];
#pragma unroll
    for (int i = 0; i < 4; i++)
#pragma unroll
        for (int j = 0; j < 4; j++)
#pragma unroll
            for (int c = 0; c < 4; c++) acc[i][j][c] = 0.f;

    load_step(0, 0);
    load_step(1, 1);

    const int a_row = (lane & 15), a_koff = (lane >> 4) * 8;
    const int b_row = (lane & 7),  b_koff = ((lane >> 3) & 1) * 8;

    for (int step = 0; step < 96; step++) {
        const int buf = step & 1;
        if (step < 95) asm volatile("cp.async.wait_group 1;" ::: "memory");
        else           asm volatile("cp.async.wait_group 0;" ::: "memory");
        __syncthreads();

        const uint32_t abase = sA0 + buf * (BM * KSTRIDE * 2);
        const uint32_t bbase = sB0 + buf * (BN * KSTRIDE * 2);
#pragma unroll
        for (int k16 = 0; k16 < BK; k16 += 16) {
            uint32_t a[4][4];
#pragma unroll
            for (int mi = 0; mi < 4; mi++)
                ldsm_x4(a[mi][0], a[mi][1], a[mi][2], a[mi][3],
                        abase + ((wm * 64 + mi * 16 + a_row) * KSTRIDE + k16 + a_koff) * 2);
#pragma unroll
            for (int ni = 0; ni < 4; ni++) {
                uint32_t b0, b1;
                ldsm_x2(b0, b1,
                        bbase + ((wn * 32 + ni * 8 + b_row) * KSTRIDE + k16 + b_koff) * 2);
#pragma unroll
                for (int mi = 0; mi < 4; mi++)
                    mma_bf16(acc[mi][ni], a[mi], b0, b1);
            }
        }
        __syncthreads();
        if (step + 2 < 96) load_step(step + 2, buf);
    }

    // ---------------- epilogue ----------------
    const int gid = lane >> 2, tig = lane & 3;
#pragma unroll
    for (int mi = 0; mi < 4; mi++) {
#pragma unroll
        for (int half = 0; half < 2; half++) {
            const int m = m0 + wm * 64 + mi * 16 + gid + half * 8;
            const int bb = m >> 11, s = m & 2047;
#pragma unroll
            for (int ni = 0; ni < 4; ni++) {
                const int n = n0 + wn * 32 + ni * 8 + tig * 2;
                float c0 = acc[mi][ni][half * 2 + 0] + bias[n];
                float c1 = acc[mi][ni][half * 2 + 1] + bias[n + 1];
                if (mode == 0) {
                    const int h = n >> 6, d = n & 63;
                    size_t o = (((size_t)bb * N_HEADS + h) * S_LEN + s) * DK + d;
                    if (z == 0) {
                        __nv_bfloat16 h0,l0,h1,l1;
                        split1(c0 * 0.125f, h0, l0);
                        split1(c1 * 0.125f, h1, l1);
                        *(__nv_bfloat162*)&g_Qbh[o] = __nv_bfloat162(h0, h1);
                        *(__nv_bfloat162*)&g_Qbl[o] = __nv_bfloat162(l0, l1);
                    } else if (z == 1) {
                        c0 += kpe[((size_t)h * DK + d) * S_LEN + s];
                        c1 += kpe[((size_t)h * DK + d + 1) * S_LEN + s];
                        __nv_bfloat16 h0,l0,h1,l1;
                        split1(c0, h0, l0);
                        split1(c1, h1, l1);
                        *(__nv_bfloat162*)&g_Kbh[o] = __nv_bfloat162(h0, h1);
                        *(__nv_bfloat162*)&g_Kbl[o] = __nv_bfloat162(l0, l1);
                    } else {
                        *(float2*)&g_Vh[o] = make_float2(c0, c1);
                    }
                } else {
                    *(float2*)&out_final[(size_t)m * D_MODEL + n] = make_float2(c0, c1);
                }
            }
        }
    }
}

// ======================= tensor-core flash attention =======================
// CTA: 128 queries x one (b,h). 256 threads = 8 warps, warp grid 4(m) x 2(n).
// K-tiles of 64. Q fragments register-resident for all tiles.
#define AT_KSTR 72
#define AT_SSTR 68
#define OFF_Q   0
#define OFF_KH  18432
#define OFF_KL  (OFF_KH + 2*9216)
#define OFF_VH  (OFF_KL + 2*9216)
#define OFF_VL  (OFF_VH + 2*9216)
#define OFF_SF  (OFF_VL + 2*9216)
#define OFF_PH  (OFF_SF + 34816)
#define OFF_PL  (OFF_PH + 18432)
#define OFF_MR  (OFF_PL + 18432)
#define OFF_LR  (OFF_MR + 512)
#define OFF_CR  (OFF_LR + 512)
#define ATTN_SMEM2 (OFF_CR + 512)

__global__ __launch_bounds__(256)
void attn_mma_kernel()
{
    extern __shared__ char smc[];
    const uint32_t base = smem_u32(smc);
    float* mrow = (float*)(smc + OFF_MR);
    float* lrow = (float*)(smc + OFF_LR);
    float* crow = (float*)(smc + OFF_CR);

    const int tid = threadIdx.x;
    const int wid = tid >> 5, lane = tid & 31;
    const int wm = wid & 3, wn = wid >> 2;      // 4 m-tiles x 2 n-tiles, warp tile 32x32
    const int q0 = blockIdx.x * 128;
    const int h = blockIdx.y, bz = blockIdx.z;
    const int bh = bz * N_HEADS + h;

    const int a_row = (lane & 15), a_koff = (lane >> 4) * 8;
    const int b_row = (lane & 7),  b_koff = ((lane >> 3) & 1) * 8;
    const int gid = lane >> 2, tig = lane & 3;

    if (tid < 128) { mrow[tid] = -1e30f; lrow[tid] = 0.f; }

    // ---- stage Q and load register fragments (hi then lo, shared buffer) ----
    uint32_t qh[2][4][4], ql[2][4][4];
    for (int r = 0; r < 2; r++) {
        const __nv_bfloat16* Qg = r ? g_Qbl : g_Qbh;
#pragma unroll
        for (int it = 0; it < 4; it++) {
            int idx = tid + it * 256;
            int row = idx >> 3, cp = idx & 7;
            cp16(base + OFF_Q + (row * AT_KSTR + cp * 8) * 2,
                 Qg + ((size_t)bh * S_LEN + q0 + row) * DK + cp * 8);
        }
        asm volatile("cp.async.commit_group;" ::: "memory");
        asm volatile("cp.async.wait_group 0;" ::: "memory");
        __syncthreads();
#pragma unroll
        for (int mi = 0; mi < 2; mi++)
#pragma unroll
            for (int k16 = 0; k16 < 4; k16++) {
                uint32_t* f = r ? ql[mi][k16] ? ql[mi][k16] : ql[mi][k16] : qh[mi][k16];
                f = r ? ql[mi][k16] : qh[mi][k16];
                ldsm_x4(f[0], f[1], f[2], f[3],
                        base + OFF_Q + ((wm * 32 + mi * 16 + a_row) * AT_KSTR + k16 * 16 + a_koff) * 2);
            }
        __syncthreads();
    }

    // ---- KV tile loader (4 arrays x 64 rows x 64 bf16 each) ----
    auto load_kv = [&](int T, int bufx) {
        const int t0 = T * 64;
        const __nv_bfloat16* srcs[4] = { g_Kbh, g_Kbl, g_Vth, g_Vtl };
        const uint32_t dsts[4] = { OFF_KH, OFF_KL, OFF_VH, OFF_VL };
#pragma unroll
        for (int arr = 0; arr < 4; arr++)
#pragma unroll
            for (int hf = 0; hf < 2; hf++) {
                int rem = tid + hf * 256;
                int row = rem >> 3, cp = rem & 7;
                const __nv_bfloat16* src;
                if (arr < 2) src = srcs[arr] + ((size_t)bh * S_LEN + t0 + row) * DK + cp * 8;
                else         src = srcs[arr] + ((size_t)bh * DK + row) * S_LEN + t0 + cp * 8;
                cp16(base + dsts[arr] + bufx * 9216 + (row * AT_KSTR + cp * 8) * 2, src);
            }
        asm volatile("cp.async.commit_group;" ::: "memory");
    };

    float oacc[2][4][4];
#pragma unroll
    for (int mi = 0; mi < 2; mi++)
#pragma unroll
        for (int ni = 0; ni < 4; ni++)
#pragma unroll
            for (int c = 0; c < 4; c++) oacc[mi][ni][c] = 0.f;

    load_kv(0, 0);

#pragma unroll 1
    for (int T = 0; T < 32; T++) {
        const int buf = T & 1;
        asm volatile("cp.async.wait_group 0;" ::: "memory");
        __syncthreads();
        if (T + 1 < 32) load_kv(T + 1, buf ^ 1);

        // ---- QK^T: 3 split passes ----
        float sacc[2][4][4];
#pragma unroll
        for (int mi = 0; mi < 2; mi++)
#pragma unroll
            for (int ni = 0; ni < 4; ni++)
#pragma unroll
                for (int c = 0; c < 4; c++) sacc[mi][ni][c] = 0.f;

        const uint32_t khb = base + OFF_KH + buf * 9216;
        const uint32_t klb = base + OFF_KL + buf * 9216;

        auto qk_pass = [&](uint32_t (&A)[2][4][4], uint32_t bbase) {
#pragma unroll
            for (int k16 = 0; k16 < 4; k16++) {
                uint32_t b0[4], b1[4];
#pragma unroll
                for (int ni = 0; ni < 4; ni++)
                    ldsm_x2(b0[ni], b1[ni],
                            bbase + ((wn * 32 + ni * 8 + b_row) * AT_KSTR + k16 * 16 + b_koff) * 2);
#pragma unroll
                for (int mi = 0; mi < 2; mi++)
#pragma unroll
                    for (int ni = 0; ni < 4; ni++)
                        mma_bf16(sacc[mi][ni], A[mi][k16], b0[ni], b1[ni]);
            }
        };
        qk_pass(qh, khb);
        qk_pass(qh, klb);
        qk_pass(ql, khb);

        // write scores to smem
        float* Sf = (float*)(smc + OFF_SF);
#pragma unroll
        for (int mi = 0; mi < 2; mi++)
#pragma unroll
            for (int hf = 0; hf < 2; hf++) {
                const int row = wm * 32 + mi * 16 + gid + hf * 8;
#pragma unroll
                for (int ni = 0; ni < 4; ni++) {
                    const int col = wn * 32 + ni * 8 + tig * 2;
                    *(float2*)&Sf[row * AT_SSTR + col] =
                        make_float2(sacc[mi][ni][hf * 2], sacc[mi][ni][hf * 2 + 1]);
                }
            }
        __syncthreads();

        // ---- online softmax: 2 threads per row ----
        {
            const int srow = tid >> 1, shalf = tid & 1;
            const float* Sr = (float*)(smc + OFF_SF) + srow * AT_SSTR + shalf * 32;
            __nv_bfloat16* PhR = (__nv_bfloat16*)(smc + OFF_PH) + srow * AT_KSTR + shalf * 32;
            __nv_bfloat16* PlR = (__nv_bfloat16*)(smc + OFF_PL) + srow * AT_KSTR + shalf * 32;
            float mloc = -1e30f;
#pragma unroll
            for (int i = 0; i < 32; i++) mloc = fmaxf(mloc, Sr[i]);
            mloc = fmaxf(mloc, __shfl_xor_sync(0xffffffffu, mloc, 1));
            float mold = mrow[srow];
            float mnew = fmaxf(mold, mloc);
            float corr = __expf(mold - mnew);
            float lsum = 0.f;
#pragma unroll
            for (int i = 0; i < 32; i++) {
                float p = __expf(Sr[i] - mnew);
                lsum += p;
                __nv_bfloat16 hh = __float2bfloat16_rn(p);
                PhR[i] = hh;
                PlR[i] = __float2bfloat16_rn(p - __bfloat162float(hh));
            }
            lsum += __shfl_xor_sync(0xffffffffu, lsum, 1);
            if (shalf == 0) {
                mrow[srow] = mnew;
                crow[srow] = corr;
                lrow[srow] = lrow[srow] * corr + lsum;
            }
        }
        __syncthreads();

        // ---- rescale accumulators ----
#pragma unroll
        for (int mi = 0; mi < 2; mi++) {
            float cl = crow[wm * 32 + mi * 16 + gid];
            float ch = crow[wm * 32 + mi * 16 + gid + 8];
#pragma unroll
            for (int ni = 0; ni < 4; ni++) {
                oacc[mi][ni][0] *= cl; oacc[mi][ni][1] *= cl;
                oacc[mi][ni][2] *= ch; oacc[mi][ni][3] *= ch;
            }
        }

        // ---- PV: 3 split passes ----
        const uint32_t vhb = base + OFF_VH + buf * 9216;
        const uint32_t vlb = base + OFF_VL + buf * 9216;
        uint32_t pf[2][4][4];

        auto load_p = [&](uint32_t pbase) {
#pragma unroll
            for (int mi = 0; mi < 2; mi++)
#pragma unroll
                for (int k16 = 0; k16 < 4; k16++)
                    ldsm_x4(pf[mi][k16][0], pf[mi][k16][1], pf[mi][k16][2], pf[mi][k16][3],
                            pbase + ((wm * 32 + mi * 16 + a_row) * AT_KSTR + k16 * 16 + a_koff) * 2);
        };
        auto pv_pass = [&](uint32_t bbase) {
#pragma unroll
            for (int k16 = 0; k16 < 4; k16++) {
                uint32_t b0[4], b1[4];
#pragma unroll
                for (int ni = 0; ni < 4; ni++)
                    ldsm_x2(b0[ni], b1[ni],
                            bbase + ((wn * 32 + ni * 8 + b_row) * AT_KSTR + k16 * 16 + b_koff) * 2);
#pragma unroll
                for (int mi = 0; mi < 2; mi++)
#pragma unroll
                    for (int ni = 0; ni < 4; ni++)
                        mma_bf16(oacc[mi][ni], pf[mi][k16], b0[ni], b1[ni]);
            }
        };
        load_p(base + OFF_PH);
        pv_pass(vhb);
        pv_pass(vlb);
        load_p(base + OFF_PL);
        pv_pass(vhb);
    }

    // ---- epilogue: normalize + split to bf16 hi/lo ----
#pragma unroll
    for (int mi = 0; mi < 2; mi++)
#pragma unroll
        for (int hf = 0; hf < 2; hf++) {
            const int qrow = wm * 32 + mi * 16 + gid + hf * 8;
            const int s = q0 + qrow;
            const float inv = 1.f / lrow[qrow];
#pragma unroll
            for (int ni = 0; ni < 4; ni++) {
                const int d = wn * 32 + ni * 8 + tig * 2;
                float v0 = oacc[mi][ni][hf * 2 + 0] * inv;
                float v1 = oacc[mi][ni][hf * 2 + 1] * inv;
                __nv_bfloat16 h0,l0,h1,l1;
                split1(v0, h0, l0);
                split1(v1, h1, l1);
                size_t o = ((size_t)bz * S_LEN + s) * D_MODEL + h * DK + d;
                *(__nv_bfloat162*)&g_Oh[o] = __nv_bfloat162(h0, h1);
                *(__nv_bfloat162*)&g_Ol[o] = __nv_bfloat162(l0, l1);
            }
        }
}

// =====================================================================
extern "C" void kernel_launch(void* const* d_in, const int* in_sizes, int n_in,
                              void* d_out, int out_size)
{
    const float* q   = (const float*)d_in[0];
    const float* k   = (const float*)d_in[1];
    const float* v   = (const float*)d_in[2];
    const float* kpe = (const float*)d_in[3];
    const float* Wq  = (const float*)d_in[4];
    const float* bq  = (const float*)d_in[5];
    const float* Wk  = (const float*)d_in[6];
    const float* bk  = (const float*)d_in[7];
    const float* Wv  = (const float*)d_in[8];
    const float* bv  = (const float*)d_in[9];
    const float* Wo  = (const float*)d_in[10];
    const float* bo  = (const float*)d_in[11];
    float* out = (float*)d_out;

    cudaFuncSetAttribute(attn_mma_kernel, cudaFuncAttributeMaxDynamicSharedMemorySize,
                         ATTN_SMEM2);

    // prep: split inputs + weights to bf16 hi/lo
    dim3 gs(M_ROWS * D_MODEL / 1024, 3);
    split_qkv_kernel<<<gs, 256>>>(q, k, v);
    dim3 gw(32, 32, 4);
    splitW_kernel<<<gw, dim3(32, 8)>>>(Wq, Wk, Wv, Wo);

    // Q/K/V projections
    dim3 gp(D_MODEL / BN, M_ROWS / BM, 3);
    gemm_bf16_kernel<<<gp, 256>>>(0, kpe, bq, bk, bv, bo, out);

    // V transpose + split
    dim3 gv(DK / 32, S_LEN / 32, B_SIZE * N_HEADS);
    vtrans_kernel<<<gv, dim3(32, 8)>>>();

    // attention (tensor cores)
    dim3 ga(S_LEN / 128, N_HEADS, B_SIZE);
    attn_mma_kernel<<<ga, 256, ATTN_SMEM2>>>();

    // output projection
    dim3 go(D_MODEL / BN, M_ROWS / BM, 1);
    gemm_bf16_kernel<<<go, 256>>>(1, kpe, bq, bk, bv, bo, out);
}

// round 6
// speedup vs baseline: 2.1504x; 1.3194x over previous
#include <cuda_runtime.h>
#include <cuda_bf16.h>
#include <cstdint>

#define D_MODEL 1024
#define N_HEADS 16
#define DK      64
#define B_SIZE  2
#define S_LEN   2048
#define M_ROWS  (B_SIZE * S_LEN)   // 4096

// ---------------- scratch ----------------
__device__ float g_Vh[B_SIZE * N_HEADS * S_LEN * DK];          // V head-split fp32 (pre-transpose)

__device__ __nv_bfloat16 g_Ah[3][(size_t)M_ROWS * D_MODEL];
__device__ __nv_bfloat16 g_Al[3][(size_t)M_ROWS * D_MODEL];
__device__ __nv_bfloat16 g_Oh[(size_t)M_ROWS * D_MODEL];       // attn out hi
__device__ __nv_bfloat16 g_Ol[(size_t)M_ROWS * D_MODEL];       // attn out lo
__device__ __nv_bfloat16 g_Wth[4][(size_t)D_MODEL * D_MODEL];  // W^T hi [n][k]
__device__ __nv_bfloat16 g_Wtl[4][(size_t)D_MODEL * D_MODEL];  // W^T lo [n][k]

// attention operands (bf16 split)
__device__ __nv_bfloat16 g_Qbh[(size_t)M_ROWS * D_MODEL];      // [B,H,S,DK] hi, scaled 1/8
__device__ __nv_bfloat16 g_Qbl[(size_t)M_ROWS * D_MODEL];
__device__ __nv_bfloat16 g_Kbh[(size_t)M_ROWS * D_MODEL];      // [B,H,S,DK] hi (K + kpe)
__device__ __nv_bfloat16 g_Kbl[(size_t)M_ROWS * D_MODEL];
__device__ __nv_bfloat16 g_Vth[(size_t)M_ROWS * D_MODEL];      // [B,H,DK,S] hi (transposed)
__device__ __nv_bfloat16 g_Vtl[(size_t)M_ROWS * D_MODEL];

// ======================= helpers =======================
__device__ __forceinline__ uint32_t smem_u32(const void* p) {
    uint32_t a;
    asm("{ .reg .u64 t; cvta.to.shared.u64 t, %1; cvt.u32.u64 %0, t; }" : "=r"(a) : "l"(p));
    return a;
}
__device__ __forceinline__ void cp16(uint32_t dst, const void* src) {
    asm volatile("cp.async.cg.shared.global [%0], [%1], 16;" :: "r"(dst), "l"(src));
}
__device__ __forceinline__ void ldsm_x4(uint32_t& r0, uint32_t& r1, uint32_t& r2, uint32_t& r3, uint32_t addr) {
    asm volatile("ldmatrix.sync.aligned.m8n8.x4.shared.b16 {%0,%1,%2,%3}, [%4];"
        : "=r"(r0), "=r"(r1), "=r"(r2), "=r"(r3) : "r"(addr));
}
__device__ __forceinline__ void ldsm_x2(uint32_t& r0, uint32_t& r1, uint32_t addr) {
    asm volatile("ldmatrix.sync.aligned.m8n8.x2.shared.b16 {%0,%1}, [%2];"
        : "=r"(r0), "=r"(r1) : "r"(addr));
}
__device__ __forceinline__ void mma_bf16(float* c, const uint32_t* a, uint32_t b0, uint32_t b1) {
    asm volatile("mma.sync.aligned.m16n8k16.row.col.f32.bf16.bf16.f32 "
        "{%0,%1,%2,%3}, {%4,%5,%6,%7}, {%8,%9}, {%0,%1,%2,%3};"
        : "+f"(c[0]), "+f"(c[1]), "+f"(c[2]), "+f"(c[3])
        : "r"(a[0]), "r"(a[1]), "r"(a[2]), "r"(a[3]), "r"(b0), "r"(b1));
}
__device__ __forceinline__ void split1(float x, __nv_bfloat16& h, __nv_bfloat16& l) {
    h = __float2bfloat16_rn(x);
    l = __float2bfloat16_rn(x - __bfloat162float(h));
}
__device__ __forceinline__ uint32_t pack_bf(__nv_bfloat16 a, __nv_bfloat16 b) {
    __nv_bfloat162 t(a, b);
    return *(uint32_t*)&t;
}

// ======================= split prep kernels =======================
__global__ __launch_bounds__(256) void split_qkv_kernel(
    const float* __restrict__ q, const float* __restrict__ k, const float* __restrict__ v)
{
    int z = blockIdx.y;
    const float* src = (z == 0) ? q : (z == 1) ? k : v;
    __nv_bfloat16* hi = g_Ah[z];
    __nv_bfloat16* lo = g_Al[z];
    size_t i = ((size_t)blockIdx.x * 256 + threadIdx.x) * 4;
    float4 a = *(const float4*)(src + i);
    __nv_bfloat16 h0,h1,h2,h3,l0,l1,l2,l3;
    split1(a.x,h0,l0); split1(a.y,h1,l1); split1(a.z,h2,l2); split1(a.w,h3,l3);
    *(__nv_bfloat162*)(hi+i)   = __nv_bfloat162(h0,h1);
    *(__nv_bfloat162*)(hi+i+2) = __nv_bfloat162(h2,h3);
    *(__nv_bfloat162*)(lo+i)   = __nv_bfloat162(l0,l1);
    *(__nv_bfloat162*)(lo+i+2) = __nv_bfloat162(l2,l3);
}

__global__ void splitW_kernel(
    const float* __restrict__ Wq, const float* __restrict__ Wk,
    const float* __restrict__ Wv, const float* __restrict__ Wo)
{
    __shared__ float sm[32][33];
    int z = blockIdx.z;
    const float* W = (z == 0) ? Wq : (z == 1) ? Wk : (z == 2) ? Wv : Wo;
    int n0 = blockIdx.x * 32, k0 = blockIdx.y * 32;
    int tx = threadIdx.x, ty = threadIdx.y;
#pragma unroll
    for (int i = 0; i < 4; i++)
        sm[ty + 8 * i][tx] = W[(size_t)(k0 + ty + 8 * i) * D_MODEL + n0 + tx];
    __syncthreads();
#pragma unroll
    for (int i = 0; i < 4; i++) {
        int c = ty + 8 * i;
        float vv = sm[tx][c];
        __nv_bfloat16 h, l;
        split1(vv, h, l);
        size_t o = (size_t)(n0 + c) * D_MODEL + k0 + tx;
        g_Wth[z][o] = h;
        g_Wtl[z][o] = l;
    }
}

// V transpose + split: g_Vh [B,H,S,DK] fp32 -> g_Vth/g_Vtl [B,H,DK,S] bf16
__global__ void vtrans_kernel()
{
    __shared__ float sm[32][33];
    int bh = blockIdx.z;
    int d0 = blockIdx.x * 32, s0 = blockIdx.y * 32;
    int tx = threadIdx.x, ty = threadIdx.y;
#pragma unroll
    for (int i = 0; i < 4; i++)
        sm[ty + 8 * i][tx] = g_Vh[((size_t)bh * S_LEN + s0 + ty + 8 * i) * DK + d0 + tx];
    __syncthreads();
#pragma unroll
    for (int i = 0; i < 4; i++) {
        int dl = ty + 8 * i;
        float vv = sm[tx][dl];
        __nv_bfloat16 h, l;
        split1(vv, h, l);
        size_t o = ((size_t)bh * DK + d0 + dl) * S_LEN + s0 + tx;
        g_Vth[o] = h;
        g_Vtl[o] = l;
    }
}

// ======================= mma.sync bf16 split GEMM (unchanged) =======================
#define BM 128
#define BN 128
#define BK 32
#define KSTRIDE 40

__global__ __launch_bounds__(256)
void gemm_bf16_kernel(int mode, const float* __restrict__ kpe,
                      const float* __restrict__ bq, const float* __restrict__ bk,
                      const float* __restrict__ bv, const float* __restrict__ bo,
                      float* __restrict__ out_final)
{
    __shared__ __nv_bfloat16 sA[2][BM * KSTRIDE];
    __shared__ __nv_bfloat16 sB[2][BN * KSTRIDE];

    const int z = blockIdx.z;
    const __nv_bfloat16 *Ahp, *Alp, *Whp, *Wlp;
    const float* bias;
    if (mode == 0) {
        Ahp = g_Ah[z]; Alp = g_Al[z]; Whp = g_Wth[z]; Wlp = g_Wtl[z];
        bias = (z == 0) ? bq : (z == 1) ? bk : bv;
    } else {
        Ahp = g_Oh; Alp = g_Ol; Whp = g_Wth[3]; Wlp = g_Wtl[3];
        bias = bo;
    }

    const int m0 = blockIdx.y * BM;
    const int n0 = blockIdx.x * BN;
    const int tid = threadIdx.x;
    const int wid = tid >> 5, lane = tid & 31;
    const int wm = wid & 1, wn = wid >> 1;

    const uint32_t sA0 = smem_u32(sA[0]);
    const uint32_t sB0 = smem_u32(sB[0]);
    const int lrow = tid >> 1, lcp = tid & 1;

    auto load_step = [&](int step, int buf) {
        int p = step >> 5, kc = (step & 31) * BK;
        const __nv_bfloat16* As = (p < 2) ? Ahp : Alp;
        const __nv_bfloat16* Bs = (p == 1) ? Wlp : Whp;
        const __nv_bfloat16* ag = As + (size_t)(m0 + lrow) * D_MODEL + kc + lcp * 16;
        const __nv_bfloat16* bg = Bs + (size_t)(n0 + lrow) * D_MODEL + kc + lcp * 16;
        uint32_t sa = sA0 + buf * (BM * KSTRIDE * 2) + (lrow * KSTRIDE + lcp * 16) * 2;
        uint32_t sb = sB0 + buf * (BN * KSTRIDE * 2) + (lrow * KSTRIDE + lcp * 16) * 2;
        cp16(sa, ag);       cp16(sa + 16, ag + 8);
        cp16(sb, bg);       cp16(sb + 16, bg + 8);
        asm volatile("cp.async.commit_group;" ::: "memory");
    };

    float acc[4][4][4];
#pragma unroll
    for (int i = 0; i < 4; i++)
#pragma unroll
        for (int j = 0; j < 4; j++)
#pragma unroll
            for (int c = 0; c < 4; c++) acc[i][j][c] = 0.f;

    load_step(0, 0);
    load_step(1, 1);

    const int a_row = (lane & 15), a_koff = (lane >> 4) * 8;
    const int b_row = (lane & 7),  b_koff = ((lane >> 3) & 1) * 8;

    for (int step = 0; step < 96; step++) {
        const int buf = step & 1;
        if (step < 95) asm volatile("cp.async.wait_group 1;" ::: "memory");
        else           asm volatile("cp.async.wait_group 0;" ::: "memory");
        __syncthreads();

        const uint32_t abase = sA0 + buf * (BM * KSTRIDE * 2);
        const uint32_t bbase = sB0 + buf * (BN * KSTRIDE * 2);
#pragma unroll
        for (int k16 = 0; k16 < BK; k16 += 16) {
            uint32_t a[4][4];
#pragma unroll
            for (int mi = 0; mi < 4; mi++)
                ldsm_x4(a[mi][0], a[mi][1], a[mi][2], a[mi][3],
                        abase + ((wm * 64 + mi * 16 + a_row) * KSTRIDE + k16 + a_koff) * 2);
#pragma unroll
            for (int ni = 0; ni < 4; ni++) {
                uint32_t b0, b1;
                ldsm_x2(b0, b1,
                        bbase + ((wn * 32 + ni * 8 + b_row) * KSTRIDE + k16 + b_koff) * 2);
#pragma unroll
                for (int mi = 0; mi < 4; mi++)
                    mma_bf16(acc[mi][ni], a[mi], b0, b1);
            }
        }
        __syncthreads();
        if (step + 2 < 96) load_step(step + 2, buf);
    }

    const int gid = lane >> 2, tig = lane & 3;
#pragma unroll
    for (int mi = 0; mi < 4; mi++) {
#pragma unroll
        for (int half = 0; half < 2; half++) {
            const int m = m0 + wm * 64 + mi * 16 + gid + half * 8;
            const int bb = m >> 11, s = m & 2047;
#pragma unroll
            for (int ni = 0; ni < 4; ni++) {
                const int n = n0 + wn * 32 + ni * 8 + tig * 2;
                float c0 = acc[mi][ni][half * 2 + 0] + bias[n];
                float c1 = acc[mi][ni][half * 2 + 1] + bias[n + 1];
                if (mode == 0) {
                    const int h = n >> 6, d = n & 63;
                    size_t o = (((size_t)bb * N_HEADS + h) * S_LEN + s) * DK + d;
                    if (z == 0) {
                        __nv_bfloat16 h0,l0,h1,l1;
                        split1(c0 * 0.125f, h0, l0);
                        split1(c1 * 0.125f, h1, l1);
                        *(__nv_bfloat162*)&g_Qbh[o] = __nv_bfloat162(h0, h1);
                        *(__nv_bfloat162*)&g_Qbl[o] = __nv_bfloat162(l0, l1);
                    } else if (z == 1) {
                        c0 += kpe[((size_t)h * DK + d) * S_LEN + s];
                        c1 += kpe[((size_t)h * DK + d + 1) * S_LEN + s];
                        __nv_bfloat16 h0,l0,h1,l1;
                        split1(c0, h0, l0);
                        split1(c1, h1, l1);
                        *(__nv_bfloat162*)&g_Kbh[o] = __nv_bfloat162(h0, h1);
                        *(__nv_bfloat162*)&g_Kbl[o] = __nv_bfloat162(l0, l1);
                    } else {
                        *(float2*)&g_Vh[o] = make_float2(c0, c1);
                    }
                } else {
                    *(float2*)&out_final[(size_t)m * D_MODEL + n] = make_float2(c0, c1);
                }
            }
        }
    }
}

// ======================= register-resident tensor-core flash attention =======================
// CTA: 128 queries x one (b,h). 8 warps, each owns 16 query rows x full 64-key tile.
// P stays in registers (QK accumulator frag == PV A-operand frag). 1 syncthreads/tile.
#define AT_KSTR 72
#define AQ_OFF  0
#define AKH_OFF 18432
#define AKL_OFF (AKH_OFF + 2 * 9216)
#define AVH_OFF (AKL_OFF + 2 * 9216)
#define AVL_OFF (AVH_OFF + 2 * 9216)
#define ATTN_SMEM3 (AVL_OFF + 2 * 9216)   // 92160 B

__global__ __launch_bounds__(256)
void attn_mma_kernel()
{
    extern __shared__ char smc[];
    const uint32_t base = smem_u32(smc);

    const int tid = threadIdx.x;
    const int wid = tid >> 5, lane = tid & 31;
    const int q0 = blockIdx.x * 128;
    const int h = blockIdx.y, bz = blockIdx.z;
    const int bh = bz * N_HEADS + h;

    const int a_row = (lane & 15), a_koff = (lane >> 4) * 8;
    // ldsm_x4 B mapping: m0,m1 = rows n..n+7 at k,k+8; m2,m3 = rows n+8..n+15 at k,k+8
    const int b_row4 = (lane & 7) + ((lane >> 4) << 3);
    const int b_koff4 = ((lane >> 3) & 1) * 8;
    const int gid = lane >> 2, tig = lane & 3;

    // ---- load Q fragments (hi then lo through shared staging buffer) ----
    uint32_t qh[4][4], ql[4][4];
    for (int r = 0; r < 2; r++) {
        const __nv_bfloat16* Qg = r ? g_Qbl : g_Qbh;
#pragma unroll
        for (int it = 0; it < 4; it++) {
            int idx = tid + it * 256;
            int row = idx >> 3, cp = idx & 7;
            cp16(base + AQ_OFF + (row * AT_KSTR + cp * 8) * 2,
                 Qg + ((size_t)bh * S_LEN + q0 + row) * DK + cp * 8);
        }
        asm volatile("cp.async.commit_group;" ::: "memory");
        asm volatile("cp.async.wait_group 0;" ::: "memory");
        __syncthreads();
#pragma unroll
        for (int k16 = 0; k16 < 4; k16++) {
            uint32_t* f = r ? ql[k16] : qh[k16];
            ldsm_x4(f[0], f[1], f[2], f[3],
                    base + AQ_OFF + ((wid * 16 + a_row) * AT_KSTR + k16 * 16 + a_koff) * 2);
        }
        __syncthreads();
    }

    // ---- KV tile loader ----
    auto load_kv = [&](int T, int bufx) {
        const int t0 = T * 64;
        const __nv_bfloat16* srcs[4] = { g_Kbh, g_Kbl, g_Vth, g_Vtl };
        const uint32_t dsts[4] = { AKH_OFF, AKL_OFF, AVH_OFF, AVL_OFF };
#pragma unroll
        for (int arr = 0; arr < 4; arr++)
#pragma unroll
            for (int hf = 0; hf < 2; hf++) {
                int rem = tid + hf * 256;
                int row = rem >> 3, cp = rem & 7;
                const __nv_bfloat16* src;
                if (arr < 2) src = srcs[arr] + ((size_t)bh * S_LEN + t0 + row) * DK + cp * 8;
                else         src = srcs[arr] + ((size_t)bh * DK + row) * S_LEN + t0 + cp * 8;
                cp16(base + dsts[arr] + bufx * 9216 + (row * AT_KSTR + cp * 8) * 2, src);
            }
        asm volatile("cp.async.commit_group;" ::: "memory");
    };

    float oacc[8][4];
#pragma unroll
    for (int ni = 0; ni < 8; ni++)
#pragma unroll
        for (int c = 0; c < 4; c++) oacc[ni][c] = 0.f;
    float m0 = -1e30f, m1 = -1e30f, l0 = 0.f, l1 = 0.f;

    load_kv(0, 0);

#pragma unroll 1
    for (int T = 0; T < 32; T++) {
        const int buf = T & 1;
        asm volatile("cp.async.wait_group 0;" ::: "memory");
        __syncthreads();
        if (T + 1 < 32) load_kv(T + 1, buf ^ 1);

        const uint32_t khb = base + AKH_OFF + buf * 9216;
        const uint32_t klb = base + AKL_OFF + buf * 9216;
        const uint32_t vhb = base + AVH_OFF + buf * 9216;
        const uint32_t vlb = base + AVL_OFF + buf * 9216;

        // ---- QK^T: S = Qh*Kh + Qh*Kl + Ql*Kh ----
        float sacc[8][4];
#pragma unroll
        for (int ni = 0; ni < 8; ni++)
#pragma unroll
            for (int c = 0; c < 4; c++) sacc[ni][c] = 0.f;

#pragma unroll
        for (int kd = 0; kd < 4; kd++) {
            uint32_t kf[4][4];
#pragma unroll
            for (int np = 0; np < 4; np++)
                ldsm_x4(kf[np][0], kf[np][1], kf[np][2], kf[np][3],
                        khb + ((np * 16 + b_row4) * AT_KSTR + kd * 16 + b_koff4) * 2);
#pragma unroll
            for (int np = 0; np < 4; np++) {
                mma_bf16(sacc[2 * np],     qh[kd], kf[np][0], kf[np][1]);
                mma_bf16(sacc[2 * np + 1], qh[kd], kf[np][2], kf[np][3]);
            }
#pragma unroll
            for (int np = 0; np < 4; np++) {
                mma_bf16(sacc[2 * np],     ql[kd], kf[np][0], kf[np][1]);
                mma_bf16(sacc[2 * np + 1], ql[kd], kf[np][2], kf[np][3]);
            }
#pragma unroll
            for (int np = 0; np < 4; np++)
                ldsm_x4(kf[np][0], kf[np][1], kf[np][2], kf[np][3],
                        klb + ((np * 16 + b_row4) * AT_KSTR + kd * 16 + b_koff4) * 2);
#pragma unroll
            for (int np = 0; np < 4; np++) {
                mma_bf16(sacc[2 * np],     qh[kd], kf[np][0], kf[np][1]);
                mma_bf16(sacc[2 * np + 1], qh[kd], kf[np][2], kf[np][3]);
            }
        }

        // ---- register softmax (rows gid and gid+8; reduce over quad) ----
        float mx0 = -1e30f, mx1 = -1e30f;
#pragma unroll
        for (int ni = 0; ni < 8; ni++) {
            mx0 = fmaxf(mx0, fmaxf(sacc[ni][0], sacc[ni][1]));
            mx1 = fmaxf(mx1, fmaxf(sacc[ni][2], sacc[ni][3]));
        }
        mx0 = fmaxf(mx0, __shfl_xor_sync(0xffffffffu, mx0, 1));
        mx0 = fmaxf(mx0, __shfl_xor_sync(0xffffffffu, mx0, 2));
        mx1 = fmaxf(mx1, __shfl_xor_sync(0xffffffffu, mx1, 1));
        mx1 = fmaxf(mx1, __shfl_xor_sync(0xffffffffu, mx1, 2));

        const float mn0 = fmaxf(m0, mx0), mn1 = fmaxf(m1, mx1);
        const float cr0 = __expf(m0 - mn0), cr1 = __expf(m1 - mn1);
        m0 = mn0; m1 = mn1;

        float s0 = 0.f, s1 = 0.f;
#pragma unroll
        for (int ni = 0; ni < 8; ni++) {
            sacc[ni][0] = __expf(sacc[ni][0] - mn0);
            sacc[ni][1] = __expf(sacc[ni][1] - mn0);
            sacc[ni][2] = __expf(sacc[ni][2] - mn1);
            sacc[ni][3] = __expf(sacc[ni][3] - mn1);
            s0 += sacc[ni][0] + sacc[ni][1];
            s1 += sacc[ni][2] + sacc[ni][3];
        }
        s0 += __shfl_xor_sync(0xffffffffu, s0, 1);
        s0 += __shfl_xor_sync(0xffffffffu, s0, 2);
        s1 += __shfl_xor_sync(0xffffffffu, s1, 1);
        s1 += __shfl_xor_sync(0xffffffffu, s1, 2);
        l0 = l0 * cr0 + s0;
        l1 = l1 * cr1 + s1;

        // rescale accumulators
#pragma unroll
        for (int ni = 0; ni < 8; ni++) {
            oacc[ni][0] *= cr0; oacc[ni][1] *= cr0;
            oacc[ni][2] *= cr1; oacc[ni][3] *= cr1;
        }

        // ---- build P fragments (hi/lo) from sacc (frag layouts match) ----
        uint32_t ph[4][4], pl[4][4];
#pragma unroll
        for (int kt = 0; kt < 4; kt++) {
            const float* e0 = sacc[2 * kt];
            const float* e1 = sacc[2 * kt + 1];
            __nv_bfloat16 h00, l00, h01, l01, h02, l02, h03, l03;
            __nv_bfloat16 h10, l10, h11, l11, h12, l12, h13, l13;
            split1(e0[0], h00, l00); split1(e0[1], h01, l01);
            split1(e0[2], h02, l02); split1(e0[3], h03, l03);
            split1(e1[0], h10, l10); split1(e1[1], h11, l11);
            split1(e1[2], h12, l12); split1(e1[3], h13, l13);
            ph[kt][0] = pack_bf(h00, h01); ph[kt][1] = pack_bf(h02, h03);
            ph[kt][2] = pack_bf(h10, h11); ph[kt][3] = pack_bf(h12, h13);
            pl[kt][0] = pack_bf(l00, l01); pl[kt][1] = pack_bf(l02, l03);
            pl[kt][2] = pack_bf(l10, l11); pl[kt][3] = pack_bf(l12, l13);
        }

        // ---- PV: O += Ph*Vh + Pl*Vh + Ph*Vl ----
#pragma unroll
        for (int kt = 0; kt < 4; kt++) {
            uint32_t vf[4][4];
#pragma unroll
            for (int np = 0; np < 4; np++)
                ldsm_x4(vf[np][0], vf[np][1], vf[np][2], vf[np][3],
                        vhb + ((np * 16 + b_row4) * AT_KSTR + kt * 16 + b_koff4) * 2);
#pragma unroll
            for (int np = 0; np < 4; np++) {
                mma_bf16(oacc[2 * np],     ph[kt], vf[np][0], vf[np][1]);
                mma_bf16(oacc[2 * np + 1], ph[kt], vf[np][2], vf[np][3]);
            }
#pragma unroll
            for (int np = 0; np < 4; np++) {
                mma_bf16(oacc[2 * np],     pl[kt], vf[np][0], vf[np][1]);
                mma_bf16(oacc[2 * np + 1], pl[kt], vf[np][2], vf[np][3]);
            }
#pragma unroll
            for (int np = 0; np < 4; np++)
                ldsm_x4(vf[np][0], vf[np][1], vf[np][2], vf[np][3],
                        vlb + ((np * 16 + b_row4) * AT_KSTR + kt * 16 + b_koff4) * 2);
#pragma unroll
            for (int np = 0; np < 4; np++) {
                mma_bf16(oacc[2 * np],     ph[kt], vf[np][0], vf[np][1]);
                mma_bf16(oacc[2 * np + 1], ph[kt], vf[np][2], vf[np][3]);
            }
        }
    }

    // ---- epilogue: normalize + split to bf16 hi/lo ----
    const float inv0 = 1.f / l0, inv1 = 1.f / l1;
#pragma unroll
    for (int hf = 0; hf < 2; hf++) {
        const int s = q0 + wid * 16 + gid + hf * 8;
        const float inv = hf ? inv1 : inv0;
#pragma unroll
        for (int ni = 0; ni < 8; ni++) {
            const int d = ni * 8 + tig * 2;
            float v0 = oacc[ni][hf * 2 + 0] * inv;
            float v1 = oacc[ni][hf * 2 + 1] * inv;
            __nv_bfloat16 h0, lo0, h1, lo1;
            split1(v0, h0, lo0);
            split1(v1, h1, lo1);
            size_t o = ((size_t)bz * S_LEN + s) * D_MODEL + h * DK + d;
            *(__nv_bfloat162*)&g_Oh[o] = __nv_bfloat162(h0, h1);
            *(__nv_bfloat162*)&g_Ol[o] = __nv_bfloat162(lo0, lo1);
        }
    }
}

// =====================================================================
extern "C" void kernel_launch(void* const* d_in, const int* in_sizes, int n_in,
                              void* d_out, int out_size)
{
    const float* q   = (const float*)d_in[0];
    const float* k   = (const float*)d_in[1];
    const float* v   = (const float*)d_in[2];
    const float* kpe = (const float*)d_in[3];
    const float* Wq  = (const float*)d_in[4];
    const float* bq  = (const float*)d_in[5];
    const float* Wk  = (const float*)d_in[6];
    const float* bk  = (const float*)d_in[7];
    const float* Wv  = (const float*)d_in[8];
    const float* bv  = (const float*)d_in[9];
    const float* Wo  = (const float*)d_in[10];
    const float* bo  = (const float*)d_in[11];
    float* out = (float*)d_out;

    cudaFuncSetAttribute(attn_mma_kernel, cudaFuncAttributeMaxDynamicSharedMemorySize,
                         ATTN_SMEM3);

    // prep: split inputs + weights to bf16 hi/lo
    dim3 gs(M_ROWS * D_MODEL / 1024, 3);
    split_qkv_kernel<<<gs, 256>>>(q, k, v);
    dim3 gw(32, 32, 4);
    splitW_kernel<<<gw, dim3(32, 8)>>>(Wq, Wk, Wv, Wo);

    // Q/K/V projections
    dim3 gp(D_MODEL / BN, M_ROWS / BM, 3);
    gemm_bf16_kernel<<<gp, 256>>>(0, kpe, bq, bk, bv, bo, out);

    // V transpose + split
    dim3 gv(DK / 32, S_LEN / 32, B_SIZE * N_HEADS);
    vtrans_kernel<<<gv, dim3(32, 8)>>>();

    // attention (tensor cores, register-resident P)
    dim3 ga(S_LEN / 128, N_HEADS, B_SIZE);
    attn_mma_kernel<<<ga, 256, ATTN_SMEM3>>>();

    // output projection
    dim3 go(D_MODEL / BN, M_ROWS / BM, 1);
    gemm_bf16_kernel<<<go, 256>>>(1, kpe, bq, bk, bv, bo, out);
}